// round 9
// baseline (speedup 1.0000x reference)
#include <cuda_runtime.h>
#include <cstdint>

// Problem constants
#define T_STEPS 512
#define BATCH   64
#define N_IN    512
#define HID     1024

// LSNN parameters
#define DT_TAU_MEM   0.1f
#define DT_TAU_SYN   0.2f
#define DT_TAU_ADAPT 1.25e-6f
#define VTH          1.0f
#define BETA         1.8f

// ---------------------------------------------------------------------------
// Scratch
// ---------------------------------------------------------------------------
__device__ float g_curin[(size_t)T_STEPS * BATCH * HID];   // x @ w_in^T, [T,B,H]
__device__ float g_wrecT[(size_t)HID * HID];               // w_rec^T  [h' , h]
__device__ float g_winT [(size_t)N_IN * HID];              // w_in^T   [k  , h]

// ---------------------------------------------------------------------------
// Packed fp32x2 helpers
// ---------------------------------------------------------------------------
__device__ __forceinline__ unsigned long long pack_f32x2(float lo, float hi)
{
    unsigned long long r;
    asm("mov.b64 %0, {%1, %2};" : "=l"(r) : "r"(__float_as_uint(lo)), "r"(__float_as_uint(hi)));
    return r;
}
__device__ __forceinline__ void fma_f32x2(unsigned long long& d,
                                          unsigned long long a, unsigned long long b)
{
    asm("fma.rn.f32x2 %0, %1, %2, %0;" : "+l"(d) : "l"(a), "l"(b));
}
__device__ __forceinline__ void add_f32x2(unsigned long long& d, unsigned long long a)
{
    asm("add.rn.f32x2 %0, %0, %1;" : "+l"(d) : "l"(a));
}
__device__ __forceinline__ float2 unpack_f32x2(unsigned long long p)
{
    unsigned int lo, hi;
    asm("mov.b64 {%0, %1}, %2;" : "=r"(lo), "=r"(hi) : "l"(p));
    return make_float2(__uint_as_float(lo), __uint_as_float(hi));
}

// ---------------------------------------------------------------------------
// Tiled transposes writing directly to device symbols
// ---------------------------------------------------------------------------
__device__ __forceinline__ void transpose_impl(const float* __restrict__ in,
                                               float* __restrict__ out,
                                               int rows, int cols)
{
    __shared__ float tile[32][33];
    int c = blockIdx.x * 32 + threadIdx.x;
    int r = blockIdx.y * 32 + threadIdx.y;
#pragma unroll
    for (int j = 0; j < 32; j += 8) {
        if (r + j < rows && c < cols)
            tile[threadIdx.y + j][threadIdx.x] = in[(size_t)(r + j) * cols + c];
    }
    __syncthreads();
    int c2 = blockIdx.y * 32 + threadIdx.x;
    int r2 = blockIdx.x * 32 + threadIdx.y;
#pragma unroll
    for (int j = 0; j < 32; j += 8) {
        if (r2 + j < cols && c2 < rows)
            out[(size_t)(r2 + j) * rows + c2] = tile[threadIdx.x][threadIdx.y + j];
    }
}

__global__ void transpose_wrec_kernel(const float* __restrict__ w_rec)
{
    transpose_impl(w_rec, g_wrecT, HID, HID);
}

__global__ void transpose_win_kernel(const float* __restrict__ w_in)
{
    transpose_impl(w_in, g_winT, HID, N_IN);
}

// ---------------------------------------------------------------------------
// SGEMM (NN): 128x128 tile, BK=8, 256 thr, 8x8 microtile, double-buffered,
// packed f32x2 FMAs; B operands loaded directly as 64-bit packed pairs.
// ---------------------------------------------------------------------------
#define BM 128
#define BN 128
#define BK 8
#define TM 8
#define TN 8

__global__ void __launch_bounds__(256, 2)
sgemm_nn_kernel(const float* __restrict__ A)
{
    const int K = N_IN;
    const int N = HID;

    __shared__ __align__(16) float As[2][BK][BM];
    __shared__ __align__(16) float Bs[2][BK][BN];

    const int bm = blockIdx.y * BM;
    const int bn = blockIdx.x * BN;
    const int tid = threadIdx.x;

    const int arow = tid >> 1;
    const int ak   = (tid & 1) * 4;
    const int brow = tid >> 5;
    const int bcol = (tid & 31) * 4;

    const int tx = (tid & 15) * TN;
    const int ty = (tid >> 4) * TM;

    unsigned long long acc2[TM][TN / 2];
#pragma unroll
    for (int m = 0; m < TM; m++)
#pragma unroll
        for (int j = 0; j < TN / 2; j++) acc2[m][j] = 0ull;

    const float* Aptr = A + (size_t)(bm + arow) * K + ak;
    const float* Bptr = g_winT + (size_t)brow * N + bn + bcol;

    float4 av = *(const float4*)Aptr;  Aptr += BK;
    float4 bv = *(const float4*)Bptr;  Bptr += (size_t)BK * N;
    As[0][ak + 0][arow] = av.x;
    As[0][ak + 1][arow] = av.y;
    As[0][ak + 2][arow] = av.z;
    As[0][ak + 3][arow] = av.w;
    *(float4*)&Bs[0][brow][bcol] = bv;
    __syncthreads();

    const int NIT = K / BK;   // 64
    for (int k0 = 0; k0 < NIT; k0++) {
        const int cur = k0 & 1;

        if (k0 + 1 < NIT) {
            av = *(const float4*)Aptr;  Aptr += BK;
            bv = *(const float4*)Bptr;  Bptr += (size_t)BK * N;
        }

#pragma unroll
        for (int kk = 0; kk < BK; kk++) {
            // B pairs directly as packed 64-bit operands
            const unsigned long long* bsp =
                (const unsigned long long*)&Bs[cur][kk][tx];
            unsigned long long bb[TN / 2];
#pragma unroll
            for (int j = 0; j < TN / 2; j++) bb[j] = bsp[j];

#pragma unroll
            for (int m = 0; m < TM; m++) {
                float a = As[cur][kk][ty + m];
                unsigned long long a2 = pack_f32x2(a, a);
#pragma unroll
                for (int j = 0; j < TN / 2; j++)
                    fma_f32x2(acc2[m][j], a2, bb[j]);
            }
        }

        if (k0 + 1 < NIT) {
            const int nxt = cur ^ 1;
            As[nxt][ak + 0][arow] = av.x;
            As[nxt][ak + 1][arow] = av.y;
            As[nxt][ak + 2][arow] = av.z;
            As[nxt][ak + 3][arow] = av.w;
            *(float4*)&Bs[nxt][brow][bcol] = bv;
            __syncthreads();
        }
    }

    float* Cbase = g_curin + (size_t)(bm + ty) * N + bn + tx;
#pragma unroll
    for (int m = 0; m < TM; m++) {
        float* crow = Cbase + (size_t)m * N;
#pragma unroll
        for (int j = 0; j < TN / 2; j += 2) {
            float2 v0 = unpack_f32x2(acc2[m][j]);
            float2 v1 = unpack_f32x2(acc2[m][j + 1]);
            *(float4*)(crow + 2 * j) = make_float4(v0.x, v0.y, v1.x, v1.y);
        }
    }
}

// ---------------------------------------------------------------------------
// LSNN scan: 1 CTA/batch, 256 threads, 4 neurons/thread.
// Per-warp SEGMENTED spike list (no shuffle scans, positions via popc),
// ONE __syncthreads per step, 4 independent packed accumulator chains,
// gin prefetch depth 3.
// ---------------------------------------------------------------------------
#define PF_DEPTH 3

__global__ void __launch_bounds__(256, 1)
lsnn_scan_kernel(float* __restrict__ out)
{
    const int tid   = threadIdx.x;            // 0..255
    const int batch = blockIdx.x;
    const int lane  = tid & 31;
    const int wid   = tid >> 5;               // 0..7
    const int h0    = tid * 4;
    const unsigned FULL = 0xffffffffu;

    // segmented: warp w owns entries [w*128, w*128+cnt_w)
    __shared__ __align__(16) int s_list[2][HID];
    __shared__ __align__(16) int s_cnt[2][8];

    float v[4]   = {0.f, 0.f, 0.f, 0.f};
    float cur[4] = {0.f, 0.f, 0.f, 0.f};
    float bth[4] = {VTH, VTH, VTH, VTH};
    float zl[4]  = {0.f, 0.f, 0.f, 0.f};
    int buf = 0;

    const float* cin  = g_curin + (size_t)batch * HID + h0;
    float*       outp = out     + (size_t)batch * HID + h0;
    const size_t strideT = (size_t)BATCH * HID;

    if (tid < 16) s_cnt[tid >> 3][tid & 7] = 0;
    __syncthreads();

    float4 pf[PF_DEPTH];
#pragma unroll
    for (int j = 0; j < PF_DEPTH; j++)
        pf[j] = __ldg((const float4*)(cin + (size_t)j * strideT));

    for (int t = 0; t < T_STEPS; t++) {
        float4 pf_new = (t + PF_DEPTH < T_STEPS)
            ? __ldg((const float4*)(cin + (size_t)(t + PF_DEPTH) * strideT))
            : make_float4(0.f, 0.f, 0.f, 0.f);

        float4 gin = pf[0];

        // ---- recurrent gather over 8 warp segments (deterministic order) ----
        unsigned long long ra0 = 0ull, ra1 = 0ull;
        unsigned long long rb0 = 0ull, rb1 = 0ull;
        unsigned long long rc0 = 0ull, rc1 = 0ull;
        unsigned long long rd0 = 0ull, rd1 = 0ull;
        {
            int4 c0 = *(const int4*)&s_cnt[buf][0];
            int4 c1 = *(const int4*)&s_cnt[buf][4];
            const int cw[8] = {c0.x, c0.y, c0.z, c0.w, c1.x, c1.y, c1.z, c1.w};
#pragma unroll
            for (int w = 0; w < 8; w++) {
                const int* seg = &s_list[buf][w * 128];
                const int c = cw[w];
                int k = 0;
                for (; k + 4 <= c; k += 4) {
                    int4 i4 = *(const int4*)(seg + k);
                    ulonglong2 w0 = *(const ulonglong2*)(g_wrecT + (size_t)i4.x * HID + h0);
                    ulonglong2 w1 = *(const ulonglong2*)(g_wrecT + (size_t)i4.y * HID + h0);
                    ulonglong2 w2 = *(const ulonglong2*)(g_wrecT + (size_t)i4.z * HID + h0);
                    ulonglong2 w3 = *(const ulonglong2*)(g_wrecT + (size_t)i4.w * HID + h0);
                    add_f32x2(ra0, w0.x); add_f32x2(ra1, w0.y);
                    add_f32x2(rb0, w1.x); add_f32x2(rb1, w1.y);
                    add_f32x2(rc0, w2.x); add_f32x2(rc1, w2.y);
                    add_f32x2(rd0, w3.x); add_f32x2(rd1, w3.y);
                }
                for (; k < c; k++) {
                    ulonglong2 ww = *(const ulonglong2*)(g_wrecT + (size_t)seg[k] * HID + h0);
                    add_f32x2(ra0, ww.x); add_f32x2(ra1, ww.y);
                }
            }
        }
        // combine chains (fixed order → deterministic)
        add_f32x2(ra0, rb0); add_f32x2(rc0, rd0); add_f32x2(ra0, rc0);
        add_f32x2(ra1, rb1); add_f32x2(rc1, rd1); add_f32x2(ra1, rc1);

        float rec[4];
        {
            float2 a = unpack_f32x2(ra0);
            float2 b = unpack_f32x2(ra1);
            rec[0] = a.x; rec[1] = a.y; rec[2] = b.x; rec[3] = b.y;
        }
        const float ginv[4] = {gin.x, gin.y, gin.z, gin.w};

        // ---- elementwise dynamics ----
        bool z[4];
        float zf[4];
#pragma unroll
        for (int j = 0; j < 4; j++) {
            float vd   = v[j] + DT_TAU_MEM * (cur[j] - v[j]);
            float idec = cur[j] - DT_TAU_SYN * cur[j];
            float bd   = bth[j] + DT_TAU_ADAPT * (VTH - bth[j]);
            z[j]  = (vd - bd) > 0.0f;
            zf[j] = z[j] ? 1.0f : 0.0f;
            v[j]   = z[j] ? 0.0f : vd;
            bth[j] = bd + (z[j] ? BETA : 0.0f);
            cur[j] = (idec + ginv[j]) + rec[j];
            zl[j]  = zf[j];
        }

        *(float4*)(outp + (size_t)t * strideT) = make_float4(zf[0], zf[1], zf[2], zf[3]);

        // ---- publish spikes into this warp's segment (popc positions, 1 barrier) ----
        unsigned b0 = __ballot_sync(FULL, z[0]);
        unsigned b1 = __ballot_sync(FULL, z[1]);
        unsigned b2 = __ballot_sync(FULL, z[2]);
        unsigned b3 = __ballot_sync(FULL, z[3]);
        const unsigned lt = (1u << lane) - 1u;
        int p = __popc(b0 & lt) + __popc(b1 & lt) + __popc(b2 & lt) + __popc(b3 & lt);

        const int nbuf = buf ^ 1;
        int* nl = &s_list[nbuf][wid * 128];
        if (z[0]) nl[p] = h0 + 0;  p += (int)z[0];
        if (z[1]) nl[p] = h0 + 1;  p += (int)z[1];
        if (z[2]) nl[p] = h0 + 2;  p += (int)z[2];
        if (z[3]) nl[p] = h0 + 3;

        if (lane == 0)
            s_cnt[nbuf][wid] = __popc(b0) + __popc(b1) + __popc(b2) + __popc(b3);

        buf = nbuf;
        __syncthreads();   // new segments + counts visible; old buf reads done

        pf[0] = pf[1];
        pf[1] = pf[2];
        pf[2] = pf_new;
    }

    // final states: (zf, vf, if, bf) appended after outs [T,B,H]
    const size_t BH = (size_t)BATCH * HID;
    float* fbase = out + (size_t)T_STEPS * BH + (size_t)batch * HID + h0;
    *(float4*)(fbase + 0 * BH) = make_float4(zl[0], zl[1], zl[2], zl[3]);
    *(float4*)(fbase + 1 * BH) = make_float4(v[0], v[1], v[2], v[3]);
    *(float4*)(fbase + 2 * BH) = make_float4(cur[0], cur[1], cur[2], cur[3]);
    *(float4*)(fbase + 3 * BH) = make_float4(bth[0], bth[1], bth[2], bth[3]);
}

// ---------------------------------------------------------------------------
// Launch
// ---------------------------------------------------------------------------
extern "C" void kernel_launch(void* const* d_in, const int* in_sizes, int n_in,
                              void* d_out, int out_size)
{
    const float* x     = (const float*)d_in[0];  // [T, B, N_IN]
    const float* w_in  = (const float*)d_in[1];  // [H, N_IN]
    const float* w_rec = (const float*)d_in[2];  // [H, H]
    float* out = (float*)d_out;

    {
        dim3 blk(32, 8);
        dim3 g2(N_IN / 32, HID / 32);
        transpose_win_kernel<<<g2, blk>>>(w_in);
        dim3 g1(HID / 32, HID / 32);
        transpose_wrec_kernel<<<g1, blk>>>(w_rec);
    }

    {
        dim3 grid(HID / BN, (T_STEPS * BATCH) / BM);
        sgemm_nn_kernel<<<grid, 256>>>(x);
    }

    {
        lsnn_scan_kernel<<<BATCH, 256>>>(out);
    }
}

// round 10
// speedup vs baseline: 1.3668x; 1.3668x over previous
#include <cuda_runtime.h>
#include <cstdint>

// Problem constants
#define T_STEPS 512
#define BATCH   64
#define N_IN    512
#define HID     1024

// LSNN parameters
#define DT_TAU_MEM   0.1f
#define DT_TAU_SYN   0.2f
#define DT_TAU_ADAPT 1.25e-6f
#define VTH          1.0f
#define BETA         1.8f

// Fused-kernel geometry
#define N_SCAN_CTAS  64
#define N_GEMM_CTAS  232
#define N_TOTAL_CTAS (N_SCAN_CTAS + N_GEMM_CTAS)   // 296 = 148 SMs * 2
#define N_ROWBLK     256                            // (T*B)/128 row-blocks
#define N_COLBLK     8                              // HID/128
#define N_TILES      (N_ROWBLK * N_COLBLK)          // 2048

// ---------------------------------------------------------------------------
// Scratch
// ---------------------------------------------------------------------------
__device__ float g_curin[(size_t)T_STEPS * BATCH * HID];   // x @ w_in^T, [T,B,H]
__device__ float g_wrecT[(size_t)HID * HID];               // w_rec^T
__device__ float g_winT [(size_t)N_IN * HID];              // w_in^T
__device__ int   g_cnt[N_ROWBLK];                          // col-tiles done per row-block

// ---------------------------------------------------------------------------
// Packed fp32x2 helpers
// ---------------------------------------------------------------------------
__device__ __forceinline__ unsigned long long pack_f32x2(float lo, float hi)
{
    unsigned long long r;
    asm("mov.b64 %0, {%1, %2};" : "=l"(r) : "r"(__float_as_uint(lo)), "r"(__float_as_uint(hi)));
    return r;
}
__device__ __forceinline__ void fma_f32x2(unsigned long long& d,
                                          unsigned long long a, unsigned long long b)
{
    asm("fma.rn.f32x2 %0, %1, %2, %0;" : "+l"(d) : "l"(a), "l"(b));
}
__device__ __forceinline__ void add_f32x2(unsigned long long& d, unsigned long long a)
{
    asm("add.rn.f32x2 %0, %0, %1;" : "+l"(d) : "l"(a));
}
__device__ __forceinline__ float2 unpack_f32x2(unsigned long long p)
{
    unsigned int lo, hi;
    asm("mov.b64 {%0, %1}, %2;" : "=r"(lo), "=r"(hi) : "l"(p));
    return make_float2(__uint_as_float(lo), __uint_as_float(hi));
}

// ---------------------------------------------------------------------------
// Tiled transposes
// ---------------------------------------------------------------------------
__device__ __forceinline__ void transpose_impl(const float* __restrict__ in,
                                               float* __restrict__ out,
                                               int rows, int cols)
{
    __shared__ float tile[32][33];
    int c = blockIdx.x * 32 + threadIdx.x;
    int r = blockIdx.y * 32 + threadIdx.y;
#pragma unroll
    for (int j = 0; j < 32; j += 8) {
        if (r + j < rows && c < cols)
            tile[threadIdx.y + j][threadIdx.x] = in[(size_t)(r + j) * cols + c];
    }
    __syncthreads();
    int c2 = blockIdx.y * 32 + threadIdx.x;
    int r2 = blockIdx.x * 32 + threadIdx.y;
#pragma unroll
    for (int j = 0; j < 32; j += 8) {
        if (r2 + j < cols && c2 < rows)
            out[(size_t)(r2 + j) * rows + c2] = tile[threadIdx.x][threadIdx.y + j];
    }
}

__global__ void transpose_wrec_kernel(const float* __restrict__ w_rec)
{
    transpose_impl(w_rec, g_wrecT, HID, HID);
}

__global__ void transpose_win_kernel(const float* __restrict__ w_in)
{
    transpose_impl(w_in, g_winT, HID, N_IN);
}

__global__ void init_flags_kernel()
{
    if (threadIdx.x < N_ROWBLK) g_cnt[threadIdx.x] = 0;
}

// ---------------------------------------------------------------------------
// Fused kernel: 296 CTAs of 256 threads.
//   bid <  64 : LSNN scan (one CTA per batch), waits on g_cnt row-block flags
//   bid >= 64 : persistent GEMM tile loop (t-major order), publishes flags
// smem is a union: GEMM needs 16KB (As+Bs), scan needs ~8.2KB (list+counts).
// ---------------------------------------------------------------------------
#define BM 128
#define BN 128
#define BK 8
#define TM 8
#define TN 8
#define SMEM_BYTES 16896

__device__ __forceinline__ void gemm_role(unsigned char* s_raw,
                                          const float* __restrict__ A)
{
    float (*As)[BK][BM] = reinterpret_cast<float (*)[BK][BM]>(s_raw);
    float (*Bs)[BK][BN] = reinterpret_cast<float (*)[BK][BN]>(s_raw + 8192);

    const int K = N_IN;
    const int N = HID;
    const int tid = threadIdx.x;

    const int arow = tid >> 1;
    const int ak   = (tid & 1) * 4;
    const int brow = tid >> 5;
    const int bcol = (tid & 31) * 4;
    const int tx = (tid & 15) * TN;
    const int ty = (tid >> 4) * TM;

    const int gbid = blockIdx.x - N_SCAN_CTAS;

    for (int tile = gbid; tile < N_TILES; tile += N_GEMM_CTAS) {
        const int rb = tile >> 3;       // row-block (t-major: covers t = 2*rb, 2*rb+1)
        const int cb = tile & 7;
        const int bm = rb * BM;
        const int bn = cb * BN;

        unsigned long long acc2[TM][TN / 2];
#pragma unroll
        for (int m = 0; m < TM; m++)
#pragma unroll
            for (int j = 0; j < TN / 2; j++) acc2[m][j] = 0ull;

        const float* Aptr = A + (size_t)(bm + arow) * K + ak;
        const float* Bptr = g_winT + (size_t)brow * N + bn + bcol;

        float4 av = *(const float4*)Aptr;  Aptr += BK;
        float4 bv = *(const float4*)Bptr;  Bptr += (size_t)BK * N;
        As[0][ak + 0][arow] = av.x;
        As[0][ak + 1][arow] = av.y;
        As[0][ak + 2][arow] = av.z;
        As[0][ak + 3][arow] = av.w;
        *(float4*)&Bs[0][brow][bcol] = bv;
        __syncthreads();

        const int NIT = K / BK;   // 64
        for (int k0 = 0; k0 < NIT; k0++) {
            const int cur = k0 & 1;

            if (k0 + 1 < NIT) {
                av = *(const float4*)Aptr;  Aptr += BK;
                bv = *(const float4*)Bptr;  Bptr += (size_t)BK * N;
            }

#pragma unroll
            for (int kk = 0; kk < BK; kk++) {
                const unsigned long long* bsp =
                    (const unsigned long long*)&Bs[cur][kk][tx];
                unsigned long long bb[TN / 2];
#pragma unroll
                for (int j = 0; j < TN / 2; j++) bb[j] = bsp[j];

#pragma unroll
                for (int m = 0; m < TM; m++) {
                    float a = As[cur][kk][ty + m];
                    unsigned long long a2 = pack_f32x2(a, a);
#pragma unroll
                    for (int j = 0; j < TN / 2; j++)
                        fma_f32x2(acc2[m][j], a2, bb[j]);
                }
            }

            if (k0 + 1 < NIT) {
                const int nxt = cur ^ 1;
                As[nxt][ak + 0][arow] = av.x;
                As[nxt][ak + 1][arow] = av.y;
                As[nxt][ak + 2][arow] = av.z;
                As[nxt][ak + 3][arow] = av.w;
                *(float4*)&Bs[nxt][brow][bcol] = bv;
                __syncthreads();
            }
        }

        float* Cbase = g_curin + (size_t)(bm + ty) * N + bn + tx;
#pragma unroll
        for (int m = 0; m < TM; m++) {
            float* crow = Cbase + (size_t)m * N;
#pragma unroll
            for (int j = 0; j < TN / 2; j += 2) {
                float2 v0 = unpack_f32x2(acc2[m][j]);
                float2 v1 = unpack_f32x2(acc2[m][j + 1]);
                *(float4*)(crow + 2 * j) = make_float4(v0.x, v0.y, v1.x, v1.y);
            }
        }

        __syncthreads();                  // all threads' stores issued
        if (tid == 0) {
            __threadfence();              // make them device-visible
            atomicAdd(&g_cnt[rb], 1);     // publish this col-tile
        }
        __syncthreads();                  // keep smem reuse safe for next tile
    }
}

__device__ __forceinline__ void scan_role(unsigned char* s_raw,
                                          float* __restrict__ out)
{
    int  (*s_list)[HID] = reinterpret_cast<int (*)[HID]>(s_raw);       // 2 x 1024 ints
    int*  s_warpcnt     = reinterpret_cast<int*>(s_raw + 8192);        // 8 ints

    const int tid   = threadIdx.x;
    const int batch = blockIdx.x;
    const int lane  = tid & 31;
    const int wid   = tid >> 5;
    const int h0    = tid * 4;
    const unsigned FULL = 0xffffffffu;

    float v[4]   = {0.f, 0.f, 0.f, 0.f};
    float cur[4] = {0.f, 0.f, 0.f, 0.f};
    float bth[4] = {VTH, VTH, VTH, VTH};
    float zl[4]  = {0.f, 0.f, 0.f, 0.f};
    int cnt = 0;
    int buf = 0;

    const float* cin  = g_curin + (size_t)batch * HID + h0;
    float*       outp = out     + (size_t)batch * HID + h0;
    const size_t strideT = (size_t)BATCH * HID;

    float4 gin, pgin;

    for (int t = 0; t < T_STEPS; t++) {
        if ((t & 1) == 0) {
            // wait for row-block t/2 (covers steps t and t+1, all batches)
            if (tid == 0) {
                while (atomicAdd(&g_cnt[t >> 1], 0) < N_COLBLK) __nanosleep(128);
            }
            __syncthreads();
            __threadfence();   // order subsequent data loads after the flag read
            gin  = *(const float4*)(cin + (size_t)t * strideT);
            pgin = *(const float4*)(cin + (size_t)(t + 1) * strideT);
        } else {
            gin = pgin;
        }

        // recurrent input: sum of w_recT rows over previous step's spikes
        unsigned long long r01 = 0ull, r23 = 0ull;
        {
            const int* lst = s_list[buf];
            const int4* lst4 = (const int4*)lst;
            int k = 0;
            for (; k + 4 <= cnt; k += 4) {
                int4 i4 = lst4[k >> 2];
                ulonglong2 w0 = *(const ulonglong2*)(g_wrecT + (size_t)i4.x * HID + h0);
                ulonglong2 w1 = *(const ulonglong2*)(g_wrecT + (size_t)i4.y * HID + h0);
                ulonglong2 w2 = *(const ulonglong2*)(g_wrecT + (size_t)i4.z * HID + h0);
                ulonglong2 w3 = *(const ulonglong2*)(g_wrecT + (size_t)i4.w * HID + h0);
                add_f32x2(r01, w0.x); add_f32x2(r23, w0.y);
                add_f32x2(r01, w1.x); add_f32x2(r23, w1.y);
                add_f32x2(r01, w2.x); add_f32x2(r23, w2.y);
                add_f32x2(r01, w3.x); add_f32x2(r23, w3.y);
            }
            for (; k < cnt; k++) {
                ulonglong2 w = *(const ulonglong2*)(g_wrecT + (size_t)lst[k] * HID + h0);
                add_f32x2(r01, w.x); add_f32x2(r23, w.y);
            }
        }
        float rec[4];
        {
            float2 a = unpack_f32x2(r01);
            float2 b = unpack_f32x2(r23);
            rec[0] = a.x; rec[1] = a.y; rec[2] = b.x; rec[3] = b.y;
        }
        const float ginv[4] = {gin.x, gin.y, gin.z, gin.w};

        // elementwise dynamics
        bool z[4];
        float zf[4];
#pragma unroll
        for (int j = 0; j < 4; j++) {
            float vd   = v[j] + DT_TAU_MEM * (cur[j] - v[j]);
            float idec = cur[j] - DT_TAU_SYN * cur[j];
            float bd   = bth[j] + DT_TAU_ADAPT * (VTH - bth[j]);
            z[j]  = (vd - bd) > 0.0f;
            zf[j] = z[j] ? 1.0f : 0.0f;
            v[j]   = z[j] ? 0.0f : vd;
            bth[j] = bd + (z[j] ? BETA : 0.0f);
            cur[j] = (idec + ginv[j]) + rec[j];
            zl[j]  = zf[j];
        }

        *(float4*)(outp + (size_t)t * strideT) = make_float4(zf[0], zf[1], zf[2], zf[3]);

        // rebuild spike list (double-buffered, 2 barriers) — r7 structure
        int mycnt = (int)z[0] + (int)z[1] + (int)z[2] + (int)z[3];

        int inc = mycnt;
#pragma unroll
        for (int off = 1; off < 32; off *= 2) {
            int nbr = __shfl_up_sync(FULL, inc, off);
            if (lane >= off) inc += nbr;
        }
        int tex = inc - mycnt;
        if (lane == 31) s_warpcnt[wid] = inc;
        __syncthreads();

        int wc = (lane < 8) ? s_warpcnt[lane] : 0;
        int winc = wc;
#pragma unroll
        for (int off = 1; off < 8; off *= 2) {
            int nbr = __shfl_up_sync(FULL, winc, off);
            if (lane >= off) winc += nbr;
        }
        int total = __shfl_sync(FULL, winc, 7);
        int wbase = __shfl_sync(FULL, winc, wid) - __shfl_sync(FULL, wc, wid);

        const int nbuf = buf ^ 1;
        int p = wbase + tex;
        int* nl = s_list[nbuf];
        if (z[0]) nl[p++] = h0 + 0;
        if (z[1]) nl[p++] = h0 + 1;
        if (z[2]) nl[p++] = h0 + 2;
        if (z[3]) nl[p++] = h0 + 3;

        cnt = total;
        buf = nbuf;
        __syncthreads();
    }

    // final states: (zf, vf, if, bf) appended after outs [T,B,H]
    const size_t BH = (size_t)BATCH * HID;
    float* fbase = out + (size_t)T_STEPS * BH + (size_t)batch * HID + h0;
    *(float4*)(fbase + 0 * BH) = make_float4(zl[0], zl[1], zl[2], zl[3]);
    *(float4*)(fbase + 1 * BH) = make_float4(v[0], v[1], v[2], v[3]);
    *(float4*)(fbase + 2 * BH) = make_float4(cur[0], cur[1], cur[2], cur[3]);
    *(float4*)(fbase + 3 * BH) = make_float4(bth[0], bth[1], bth[2], bth[3]);
}

__global__ void __launch_bounds__(256, 2)
fused_kernel(const float* __restrict__ A, float* __restrict__ out)
{
    __shared__ __align__(16) unsigned char s_raw[SMEM_BYTES];
    if (blockIdx.x < N_SCAN_CTAS) scan_role(s_raw, out);
    else                          gemm_role(s_raw, A);
}

// ---------------------------------------------------------------------------
// Launch
// ---------------------------------------------------------------------------
extern "C" void kernel_launch(void* const* d_in, const int* in_sizes, int n_in,
                              void* d_out, int out_size)
{
    const float* x     = (const float*)d_in[0];  // [T, B, N_IN]
    const float* w_in  = (const float*)d_in[1];  // [H, N_IN]
    const float* w_rec = (const float*)d_in[2];  // [H, H]
    float* out = (float*)d_out;

    {
        dim3 blk(32, 8);
        dim3 g2(N_IN / 32, HID / 32);
        transpose_win_kernel<<<g2, blk>>>(w_in);
        dim3 g1(HID / 32, HID / 32);
        transpose_wrec_kernel<<<g1, blk>>>(w_rec);
    }

    init_flags_kernel<<<1, 256>>>();

    fused_kernel<<<N_TOTAL_CTAS, 256>>>(x, out);
}

// round 11
// speedup vs baseline: 1.3835x; 1.0123x over previous
#include <cuda_runtime.h>
#include <cstdint>

// Problem constants
#define T_STEPS 512
#define BATCH   64
#define N_IN    512
#define HID     1024

// LSNN parameters
#define DT_TAU_MEM   0.1f
#define DT_TAU_SYN   0.2f
#define DT_TAU_ADAPT 1.25e-6f
#define VTH          1.0f
#define BETA         1.8f

// Fused-kernel geometry
#define N_SCAN_CTAS  64
#define N_GEMM_CTAS  232
#define N_TOTAL_CTAS (N_SCAN_CTAS + N_GEMM_CTAS)   // 296 = 148 SMs * 2
#define N_ROWBLK     256                            // (T*B)/128 row-blocks
#define N_COLBLK     8                              // HID/128
#define N_TILES      (N_ROWBLK * N_COLBLK)          // 2048

// ---------------------------------------------------------------------------
// Scratch
// ---------------------------------------------------------------------------
__device__ float g_curin[(size_t)T_STEPS * BATCH * HID];   // x @ w_in^T, [T,B,H]
__device__ float g_wrecT[(size_t)HID * HID];               // w_rec^T
__device__ float g_winT [(size_t)N_IN * HID];              // w_in^T
__device__ int   g_cnt[N_ROWBLK];                          // col-tiles done per row-block
__device__ int   g_tile;                                   // dynamic tile queue head

// ---------------------------------------------------------------------------
// Packed fp32x2 helpers
// ---------------------------------------------------------------------------
__device__ __forceinline__ unsigned long long pack_f32x2(float lo, float hi)
{
    unsigned long long r;
    asm("mov.b64 %0, {%1, %2};" : "=l"(r) : "r"(__float_as_uint(lo)), "r"(__float_as_uint(hi)));
    return r;
}
__device__ __forceinline__ void fma_f32x2(unsigned long long& d,
                                          unsigned long long a, unsigned long long b)
{
    asm("fma.rn.f32x2 %0, %1, %2, %0;" : "+l"(d) : "l"(a), "l"(b));
}
__device__ __forceinline__ void add_f32x2(unsigned long long& d, unsigned long long a)
{
    asm("add.rn.f32x2 %0, %0, %1;" : "+l"(d) : "l"(a));
}
__device__ __forceinline__ float2 unpack_f32x2(unsigned long long p)
{
    unsigned int lo, hi;
    asm("mov.b64 {%0, %1}, %2;" : "=r"(lo), "=r"(hi) : "l"(p));
    return make_float2(__uint_as_float(lo), __uint_as_float(hi));
}

// ---------------------------------------------------------------------------
// Tiled transposes
// ---------------------------------------------------------------------------
__device__ __forceinline__ void transpose_impl(const float* __restrict__ in,
                                               float* __restrict__ out,
                                               int rows, int cols)
{
    __shared__ float tile[32][33];
    int c = blockIdx.x * 32 + threadIdx.x;
    int r = blockIdx.y * 32 + threadIdx.y;
#pragma unroll
    for (int j = 0; j < 32; j += 8) {
        if (r + j < rows && c < cols)
            tile[threadIdx.y + j][threadIdx.x] = in[(size_t)(r + j) * cols + c];
    }
    __syncthreads();
    int c2 = blockIdx.y * 32 + threadIdx.x;
    int r2 = blockIdx.x * 32 + threadIdx.y;
#pragma unroll
    for (int j = 0; j < 32; j += 8) {
        if (r2 + j < cols && c2 < rows)
            out[(size_t)(r2 + j) * rows + c2] = tile[threadIdx.x][threadIdx.y + j];
    }
}

__global__ void transpose_wrec_kernel(const float* __restrict__ w_rec)
{
    transpose_impl(w_rec, g_wrecT, HID, HID);
}

__global__ void transpose_win_kernel(const float* __restrict__ w_in)
{
    transpose_impl(w_in, g_winT, HID, N_IN);
}

__global__ void init_flags_kernel()
{
    if (threadIdx.x < N_ROWBLK) g_cnt[threadIdx.x] = 0;
    if (threadIdx.x == 0) g_tile = 0;
}

// ---------------------------------------------------------------------------
// Fused kernel: 296 CTAs of 256 threads.
//   bid <  64 : LSNN scan (one CTA per batch), waits on g_cnt row-block flags
//   bid >= 64 : GEMM worker pulling tiles from a dynamic t-ordered queue
// ---------------------------------------------------------------------------
#define BM 128
#define BN 128
#define BK 8
#define TM 8
#define TN 8
#define SMEM_BYTES 16896

__device__ __forceinline__ void gemm_role(unsigned char* s_raw,
                                          const float* __restrict__ A)
{
    float (*As)[BK][BM] = reinterpret_cast<float (*)[BK][BM]>(s_raw);
    float (*Bs)[BK][BN] = reinterpret_cast<float (*)[BK][BN]>(s_raw + 8192);
    int* s_tile = reinterpret_cast<int*>(s_raw + 16384);

    const int K = N_IN;
    const int N = HID;
    const int tid = threadIdx.x;

    const int arow = tid >> 1;
    const int ak   = (tid & 1) * 4;
    const int brow = tid >> 5;
    const int bcol = (tid & 31) * 4;
    const int tx = (tid & 15) * TN;
    const int ty = (tid >> 4) * TM;

    for (;;) {
        // grab next tile in t-major order (dynamic balance, minimal tail)
        if (tid == 0) *s_tile = atomicAdd(&g_tile, 1);
        __syncthreads();
        const int tile = *s_tile;
        __syncthreads();          // s_tile consumed before next overwrite
        if (tile >= N_TILES) break;

        const int rb = tile >> 3;       // row-block (covers t = 2*rb, 2*rb+1)
        const int cb = tile & 7;
        const int bm = rb * BM;
        const int bn = cb * BN;

        unsigned long long acc2[TM][TN / 2];
#pragma unroll
        for (int m = 0; m < TM; m++)
#pragma unroll
            for (int j = 0; j < TN / 2; j++) acc2[m][j] = 0ull;

        const float* Aptr = A + (size_t)(bm + arow) * K + ak;
        const float* Bptr = g_winT + (size_t)brow * N + bn + bcol;

        float4 av = *(const float4*)Aptr;  Aptr += BK;
        float4 bv = *(const float4*)Bptr;  Bptr += (size_t)BK * N;
        As[0][ak + 0][arow] = av.x;
        As[0][ak + 1][arow] = av.y;
        As[0][ak + 2][arow] = av.z;
        As[0][ak + 3][arow] = av.w;
        *(float4*)&Bs[0][brow][bcol] = bv;
        __syncthreads();

        const int NIT = K / BK;   // 64
        for (int k0 = 0; k0 < NIT; k0++) {
            const int cur = k0 & 1;

            if (k0 + 1 < NIT) {
                av = *(const float4*)Aptr;  Aptr += BK;
                bv = *(const float4*)Bptr;  Bptr += (size_t)BK * N;
            }

#pragma unroll
            for (int kk = 0; kk < BK; kk++) {
                const unsigned long long* bsp =
                    (const unsigned long long*)&Bs[cur][kk][tx];
                unsigned long long bb[TN / 2];
#pragma unroll
                for (int j = 0; j < TN / 2; j++) bb[j] = bsp[j];

#pragma unroll
                for (int m = 0; m < TM; m++) {
                    float a = As[cur][kk][ty + m];
                    unsigned long long a2 = pack_f32x2(a, a);
#pragma unroll
                    for (int j = 0; j < TN / 2; j++)
                        fma_f32x2(acc2[m][j], a2, bb[j]);
                }
            }

            if (k0 + 1 < NIT) {
                const int nxt = cur ^ 1;
                As[nxt][ak + 0][arow] = av.x;
                As[nxt][ak + 1][arow] = av.y;
                As[nxt][ak + 2][arow] = av.z;
                As[nxt][ak + 3][arow] = av.w;
                *(float4*)&Bs[nxt][brow][bcol] = bv;
                __syncthreads();
            }
        }

        float* Cbase = g_curin + (size_t)(bm + ty) * N + bn + tx;
#pragma unroll
        for (int m = 0; m < TM; m++) {
            float* crow = Cbase + (size_t)m * N;
#pragma unroll
            for (int j = 0; j < TN / 2; j += 2) {
                float2 v0 = unpack_f32x2(acc2[m][j]);
                float2 v1 = unpack_f32x2(acc2[m][j + 1]);
                *(float4*)(crow + 2 * j) = make_float4(v0.x, v0.y, v1.x, v1.y);
            }
        }

        __syncthreads();                  // all threads' stores issued
        if (tid == 0) {
            __threadfence();              // make them device-visible
            atomicAdd(&g_cnt[rb], 1);     // publish this col-tile
        }
        __syncthreads();                  // keep smem reuse safe for next tile
    }
}

__device__ __forceinline__ void scan_role(unsigned char* s_raw,
                                          float* __restrict__ out)
{
    int  (*s_list)[HID] = reinterpret_cast<int (*)[HID]>(s_raw);       // 2 x 1024 ints
    int*  s_warpcnt     = reinterpret_cast<int*>(s_raw + 8192);        // 8 ints

    const int tid   = threadIdx.x;
    const int batch = blockIdx.x;
    const int lane  = tid & 31;
    const int wid   = tid >> 5;
    const int h0    = tid * 4;
    const unsigned FULL = 0xffffffffu;

    float v[4]   = {0.f, 0.f, 0.f, 0.f};
    float cur[4] = {0.f, 0.f, 0.f, 0.f};
    float bth[4] = {VTH, VTH, VTH, VTH};
    float zl[4]  = {0.f, 0.f, 0.f, 0.f};
    int cnt = 0;
    int buf = 0;

    const float* cin  = g_curin + (size_t)batch * HID + h0;
    float*       outp = out     + (size_t)batch * HID + h0;
    const size_t strideT = (size_t)BATCH * HID;

    float4 gin, pgin;

    for (int t = 0; t < T_STEPS; t++) {
        if ((t & 1) == 0) {
            // wait for row-block t/2 (covers steps t and t+1, all batches)
            if (tid == 0) {
                int* flag = &g_cnt[t >> 1];
                int c;
                for (;;) {
                    asm volatile("ld.acquire.gpu.global.b32 %0, [%1];"
                                 : "=r"(c) : "l"(flag) : "memory");
                    if (c >= N_COLBLK) break;
                    __nanosleep(256);
                }
            }
            __syncthreads();
            __threadfence();   // order subsequent data loads after the flag read
            gin  = *(const float4*)(cin + (size_t)t * strideT);
            pgin = *(const float4*)(cin + (size_t)(t + 1) * strideT);
        } else {
            gin = pgin;
        }

        // recurrent input: sum of w_recT rows over previous step's spikes
        unsigned long long r01 = 0ull, r23 = 0ull;
        {
            const int* lst = s_list[buf];
            const int4* lst4 = (const int4*)lst;
            int k = 0;
            for (; k + 4 <= cnt; k += 4) {
                int4 i4 = lst4[k >> 2];
                ulonglong2 w0 = *(const ulonglong2*)(g_wrecT + (size_t)i4.x * HID + h0);
                ulonglong2 w1 = *(const ulonglong2*)(g_wrecT + (size_t)i4.y * HID + h0);
                ulonglong2 w2 = *(const ulonglong2*)(g_wrecT + (size_t)i4.z * HID + h0);
                ulonglong2 w3 = *(const ulonglong2*)(g_wrecT + (size_t)i4.w * HID + h0);
                add_f32x2(r01, w0.x); add_f32x2(r23, w0.y);
                add_f32x2(r01, w1.x); add_f32x2(r23, w1.y);
                add_f32x2(r01, w2.x); add_f32x2(r23, w2.y);
                add_f32x2(r01, w3.x); add_f32x2(r23, w3.y);
            }
            for (; k < cnt; k++) {
                ulonglong2 w = *(const ulonglong2*)(g_wrecT + (size_t)lst[k] * HID + h0);
                add_f32x2(r01, w.x); add_f32x2(r23, w.y);
            }
        }
        float rec[4];
        {
            float2 a = unpack_f32x2(r01);
            float2 b = unpack_f32x2(r23);
            rec[0] = a.x; rec[1] = a.y; rec[2] = b.x; rec[3] = b.y;
        }
        const float ginv[4] = {gin.x, gin.y, gin.z, gin.w};

        // elementwise dynamics
        bool z[4];
        float zf[4];
#pragma unroll
        for (int j = 0; j < 4; j++) {
            float vd   = v[j] + DT_TAU_MEM * (cur[j] - v[j]);
            float idec = cur[j] - DT_TAU_SYN * cur[j];
            float bd   = bth[j] + DT_TAU_ADAPT * (VTH - bth[j]);
            z[j]  = (vd - bd) > 0.0f;
            zf[j] = z[j] ? 1.0f : 0.0f;
            v[j]   = z[j] ? 0.0f : vd;
            bth[j] = bd + (z[j] ? BETA : 0.0f);
            cur[j] = (idec + ginv[j]) + rec[j];
            zl[j]  = zf[j];
        }

        *(float4*)(outp + (size_t)t * strideT) = make_float4(zf[0], zf[1], zf[2], zf[3]);

        // rebuild spike list (double-buffered, 2 barriers)
        int mycnt = (int)z[0] + (int)z[1] + (int)z[2] + (int)z[3];

        int inc = mycnt;
#pragma unroll
        for (int off = 1; off < 32; off *= 2) {
            int nbr = __shfl_up_sync(FULL, inc, off);
            if (lane >= off) inc += nbr;
        }
        int tex = inc - mycnt;
        if (lane == 31) s_warpcnt[wid] = inc;
        __syncthreads();

        int wc = (lane < 8) ? s_warpcnt[lane] : 0;
        int winc = wc;
#pragma unroll
        for (int off = 1; off < 8; off *= 2) {
            int nbr = __shfl_up_sync(FULL, winc, off);
            if (lane >= off) winc += nbr;
        }
        int total = __shfl_sync(FULL, winc, 7);
        int wbase = __shfl_sync(FULL, winc, wid) - __shfl_sync(FULL, wc, wid);

        const int nbuf = buf ^ 1;
        int p = wbase + tex;
        int* nl = s_list[nbuf];
        if (z[0]) nl[p++] = h0 + 0;
        if (z[1]) nl[p++] = h0 + 1;
        if (z[2]) nl[p++] = h0 + 2;
        if (z[3]) nl[p++] = h0 + 3;

        cnt = total;
        buf = nbuf;
        __syncthreads();
    }

    // final states: (zf, vf, if, bf) appended after outs [T,B,H]
    const size_t BH = (size_t)BATCH * HID;
    float* fbase = out + (size_t)T_STEPS * BH + (size_t)batch * HID + h0;
    *(float4*)(fbase + 0 * BH) = make_float4(zl[0], zl[1], zl[2], zl[3]);
    *(float4*)(fbase + 1 * BH) = make_float4(v[0], v[1], v[2], v[3]);
    *(float4*)(fbase + 2 * BH) = make_float4(cur[0], cur[1], cur[2], cur[3]);
    *(float4*)(fbase + 3 * BH) = make_float4(bth[0], bth[1], bth[2], bth[3]);
}

__global__ void __launch_bounds__(256, 2)
fused_kernel(const float* __restrict__ A, float* __restrict__ out)
{
    __shared__ __align__(16) unsigned char s_raw[SMEM_BYTES];
    if (blockIdx.x < N_SCAN_CTAS) scan_role(s_raw, out);
    else                          gemm_role(s_raw, A);
}

// ---------------------------------------------------------------------------
// Launch
// ---------------------------------------------------------------------------
extern "C" void kernel_launch(void* const* d_in, const int* in_sizes, int n_in,
                              void* d_out, int out_size)
{
    const float* x     = (const float*)d_in[0];  // [T, B, N_IN]
    const float* w_in  = (const float*)d_in[1];  // [H, N_IN]
    const float* w_rec = (const float*)d_in[2];  // [H, H]
    float* out = (float*)d_out;

    {
        dim3 blk(32, 8);
        dim3 g2(N_IN / 32, HID / 32);
        transpose_win_kernel<<<g2, blk>>>(w_in);
        dim3 g1(HID / 32, HID / 32);
        transpose_wrec_kernel<<<g1, blk>>>(w_rec);
    }

    init_flags_kernel<<<1, 256>>>();

    fused_kernel<<<N_TOTAL_CTAS, 256>>>(x, out);
}

// round 12
// speedup vs baseline: 1.3946x; 1.0080x over previous
#include <cuda_runtime.h>
#include <cstdint>

// Problem constants
#define T_STEPS 512
#define BATCH   64
#define N_IN    512
#define HID     1024

// LSNN parameters
#define DT_TAU_MEM   0.1f
#define DT_TAU_SYN   0.2f
#define DT_TAU_ADAPT 1.25e-6f
#define VTH          1.0f
#define BETA         1.8f

// Fused-kernel geometry
#define N_SCAN_CTAS  64
#define N_GEMM_CTAS  232
#define N_TOTAL_CTAS (N_SCAN_CTAS + N_GEMM_CTAS)   // 296 = 148 SMs * 2
#define N_ROWBLK     256                            // (T*B)/128 row-blocks
#define N_COLBLK     8                              // HID/128
#define N_TILES      (N_ROWBLK * N_COLBLK)          // 2048

// ---------------------------------------------------------------------------
// Scratch
// ---------------------------------------------------------------------------
__device__ float g_curin[(size_t)T_STEPS * BATCH * HID];   // x @ w_in^T, [T,B,H]
__device__ float g_wrecT[(size_t)HID * HID];               // w_rec^T
__device__ float g_winT [(size_t)N_IN * HID];              // w_in^T
__device__ int   g_cnt[N_ROWBLK];                          // col-tiles done per row-block
__device__ int   g_tile;                                   // dynamic tile queue head

// ---------------------------------------------------------------------------
// Packed fp32x2 helpers
// ---------------------------------------------------------------------------
__device__ __forceinline__ unsigned long long pack_f32x2(float lo, float hi)
{
    unsigned long long r;
    asm("mov.b64 %0, {%1, %2};" : "=l"(r) : "r"(__float_as_uint(lo)), "r"(__float_as_uint(hi)));
    return r;
}
__device__ __forceinline__ void fma_f32x2(unsigned long long& d,
                                          unsigned long long a, unsigned long long b)
{
    asm("fma.rn.f32x2 %0, %1, %2, %0;" : "+l"(d) : "l"(a), "l"(b));
}
__device__ __forceinline__ void add_f32x2(unsigned long long& d, unsigned long long a)
{
    asm("add.rn.f32x2 %0, %0, %1;" : "+l"(d) : "l"(a));
}
__device__ __forceinline__ float2 unpack_f32x2(unsigned long long p)
{
    unsigned int lo, hi;
    asm("mov.b64 {%0, %1}, %2;" : "=r"(lo), "=r"(hi) : "l"(p));
    return make_float2(__uint_as_float(lo), __uint_as_float(hi));
}

// ---------------------------------------------------------------------------
// Tiled transposes
// ---------------------------------------------------------------------------
__device__ __forceinline__ void transpose_impl(const float* __restrict__ in,
                                               float* __restrict__ out,
                                               int rows, int cols)
{
    __shared__ float tile[32][33];
    int c = blockIdx.x * 32 + threadIdx.x;
    int r = blockIdx.y * 32 + threadIdx.y;
#pragma unroll
    for (int j = 0; j < 32; j += 8) {
        if (r + j < rows && c < cols)
            tile[threadIdx.y + j][threadIdx.x] = in[(size_t)(r + j) * cols + c];
    }
    __syncthreads();
    int c2 = blockIdx.y * 32 + threadIdx.x;
    int r2 = blockIdx.x * 32 + threadIdx.y;
#pragma unroll
    for (int j = 0; j < 32; j += 8) {
        if (r2 + j < cols && c2 < rows)
            out[(size_t)(r2 + j) * rows + c2] = tile[threadIdx.x][threadIdx.y + j];
    }
}

__global__ void transpose_wrec_kernel(const float* __restrict__ w_rec)
{
    transpose_impl(w_rec, g_wrecT, HID, HID);
}

__global__ void transpose_win_kernel(const float* __restrict__ w_in)
{
    transpose_impl(w_in, g_winT, HID, N_IN);
}

__global__ void init_flags_kernel()
{
    if (threadIdx.x < N_ROWBLK) g_cnt[threadIdx.x] = 0;
    if (threadIdx.x == 0) g_tile = 0;
}

// ---------------------------------------------------------------------------
// Fused kernel: 296 CTAs of 256 threads.
//   bid <  64 : LSNN scan (one CTA per batch), waits on g_cnt row-block flags
//   bid >= 64 : GEMM worker pulling tiles from a dynamic t-ordered queue
// ---------------------------------------------------------------------------
#define BM 128
#define BN 128
#define BK 8
#define TM 8
#define TN 8
#define SMEM_BYTES 16896

__device__ __forceinline__ void gemm_role(unsigned char* s_raw,
                                          const float* __restrict__ A)
{
    float (*As)[BK][BM] = reinterpret_cast<float (*)[BK][BM]>(s_raw);
    float (*Bs)[BK][BN] = reinterpret_cast<float (*)[BK][BN]>(s_raw + 8192);
    int* s_tile = reinterpret_cast<int*>(s_raw + 16384);

    const int K = N_IN;
    const int N = HID;
    const int tid = threadIdx.x;

    const int arow = tid >> 1;
    const int ak   = (tid & 1) * 4;
    const int brow = tid >> 5;
    const int bcol = (tid & 31) * 4;
    const int tx = (tid & 15) * TN;
    const int ty = (tid >> 4) * TM;

    for (;;) {
        // grab next tile in t-major order (dynamic balance, minimal tail)
        if (tid == 0) *s_tile = atomicAdd(&g_tile, 1);
        __syncthreads();
        const int tile = *s_tile;
        __syncthreads();          // s_tile consumed before next overwrite
        if (tile >= N_TILES) break;

        const int rb = tile >> 3;       // row-block (covers t = 2*rb, 2*rb+1)
        const int cb = tile & 7;
        const int bm = rb * BM;
        const int bn = cb * BN;

        unsigned long long acc2[TM][TN / 2];
#pragma unroll
        for (int m = 0; m < TM; m++)
#pragma unroll
            for (int j = 0; j < TN / 2; j++) acc2[m][j] = 0ull;

        const float* Aptr = A + (size_t)(bm + arow) * K + ak;
        const float* Bptr = g_winT + (size_t)brow * N + bn + bcol;

        float4 av = *(const float4*)Aptr;  Aptr += BK;
        float4 bv = *(const float4*)Bptr;  Bptr += (size_t)BK * N;
        As[0][ak + 0][arow] = av.x;
        As[0][ak + 1][arow] = av.y;
        As[0][ak + 2][arow] = av.z;
        As[0][ak + 3][arow] = av.w;
        *(float4*)&Bs[0][brow][bcol] = bv;
        __syncthreads();

        const int NIT = K / BK;   // 64
        for (int k0 = 0; k0 < NIT; k0++) {
            const int cur = k0 & 1;

            if (k0 + 1 < NIT) {
                av = *(const float4*)Aptr;  Aptr += BK;
                bv = *(const float4*)Bptr;  Bptr += (size_t)BK * N;
            }

#pragma unroll
            for (int kk = 0; kk < BK; kk++) {
                // A: 2 x LDS.128 (broadcast), then register packs (MOV pipe)
                const float4* asp = (const float4*)&As[cur][kk][ty];
                float4 a0 = asp[0];
                float4 a1 = asp[1];
                unsigned long long a2[TM];
                a2[0] = pack_f32x2(a0.x, a0.x);
                a2[1] = pack_f32x2(a0.y, a0.y);
                a2[2] = pack_f32x2(a0.z, a0.z);
                a2[3] = pack_f32x2(a0.w, a0.w);
                a2[4] = pack_f32x2(a1.x, a1.x);
                a2[5] = pack_f32x2(a1.y, a1.y);
                a2[6] = pack_f32x2(a1.z, a1.z);
                a2[7] = pack_f32x2(a1.w, a1.w);

                // B: 2 x LDS.128 (conflict-free, 128B span per warp)
                const ulonglong2* bsp = (const ulonglong2*)&Bs[cur][kk][tx];
                ulonglong2 bq0 = bsp[0];
                ulonglong2 bq1 = bsp[1];
                unsigned long long bb[TN / 2] = {bq0.x, bq0.y, bq1.x, bq1.y};

#pragma unroll
                for (int m = 0; m < TM; m++)
#pragma unroll
                    for (int j = 0; j < TN / 2; j++)
                        fma_f32x2(acc2[m][j], a2[m], bb[j]);
            }

            if (k0 + 1 < NIT) {
                const int nxt = cur ^ 1;
                As[nxt][ak + 0][arow] = av.x;
                As[nxt][ak + 1][arow] = av.y;
                As[nxt][ak + 2][arow] = av.z;
                As[nxt][ak + 3][arow] = av.w;
                *(float4*)&Bs[nxt][brow][bcol] = bv;
                __syncthreads();
            }
        }

        float* Cbase = g_curin + (size_t)(bm + ty) * N + bn + tx;
#pragma unroll
        for (int m = 0; m < TM; m++) {
            float* crow = Cbase + (size_t)m * N;
#pragma unroll
            for (int j = 0; j < TN / 2; j += 2) {
                float2 v0 = unpack_f32x2(acc2[m][j]);
                float2 v1 = unpack_f32x2(acc2[m][j + 1]);
                *(float4*)(crow + 2 * j) = make_float4(v0.x, v0.y, v1.x, v1.y);
            }
        }

        __syncthreads();                  // all threads' stores issued
        if (tid == 0) {
            __threadfence();              // make them device-visible
            atomicAdd(&g_cnt[rb], 1);     // publish this col-tile
        }
        __syncthreads();                  // keep smem reuse safe for next tile
    }
}

__device__ __forceinline__ void scan_role(unsigned char* s_raw,
                                          float* __restrict__ out)
{
    int  (*s_list)[HID] = reinterpret_cast<int (*)[HID]>(s_raw);       // 2 x 1024 ints
    int*  s_warpcnt     = reinterpret_cast<int*>(s_raw + 8192);        // 8 ints

    const int tid   = threadIdx.x;
    const int batch = blockIdx.x;
    const int lane  = tid & 31;
    const int wid   = tid >> 5;
    const int h0    = tid * 4;
    const unsigned FULL = 0xffffffffu;

    float v[4]   = {0.f, 0.f, 0.f, 0.f};
    float cur[4] = {0.f, 0.f, 0.f, 0.f};
    float bth[4] = {VTH, VTH, VTH, VTH};
    float zl[4]  = {0.f, 0.f, 0.f, 0.f};
    int cnt = 0;
    int buf = 0;

    const float* cin  = g_curin + (size_t)batch * HID + h0;
    float*       outp = out     + (size_t)batch * HID + h0;
    const size_t strideT = (size_t)BATCH * HID;

    float4 gin, pgin;

    for (int t = 0; t < T_STEPS; t++) {
        if ((t & 1) == 0) {
            // wait for row-block t/2 (covers steps t and t+1, all batches)
            if (tid == 0) {
                int* flag = &g_cnt[t >> 1];
                int c;
                for (;;) {
                    asm volatile("ld.acquire.gpu.global.b32 %0, [%1];"
                                 : "=r"(c) : "l"(flag) : "memory");
                    if (c >= N_COLBLK) break;
                    __nanosleep(256);
                }
            }
            __syncthreads();
            __threadfence();   // order subsequent data loads after the flag read
            gin  = *(const float4*)(cin + (size_t)t * strideT);
            pgin = *(const float4*)(cin + (size_t)(t + 1) * strideT);
        } else {
            gin = pgin;
        }

        // recurrent input: sum of w_recT rows over previous step's spikes
        unsigned long long r01 = 0ull, r23 = 0ull;
        {
            const int* lst = s_list[buf];
            const int4* lst4 = (const int4*)lst;
            int k = 0;
            for (; k + 4 <= cnt; k += 4) {
                int4 i4 = lst4[k >> 2];
                ulonglong2 w0 = *(const ulonglong2*)(g_wrecT + (size_t)i4.x * HID + h0);
                ulonglong2 w1 = *(const ulonglong2*)(g_wrecT + (size_t)i4.y * HID + h0);
                ulonglong2 w2 = *(const ulonglong2*)(g_wrecT + (size_t)i4.z * HID + h0);
                ulonglong2 w3 = *(const ulonglong2*)(g_wrecT + (size_t)i4.w * HID + h0);
                add_f32x2(r01, w0.x); add_f32x2(r23, w0.y);
                add_f32x2(r01, w1.x); add_f32x2(r23, w1.y);
                add_f32x2(r01, w2.x); add_f32x2(r23, w2.y);
                add_f32x2(r01, w3.x); add_f32x2(r23, w3.y);
            }
            for (; k < cnt; k++) {
                ulonglong2 w = *(const ulonglong2*)(g_wrecT + (size_t)lst[k] * HID + h0);
                add_f32x2(r01, w.x); add_f32x2(r23, w.y);
            }
        }
        float rec[4];
        {
            float2 a = unpack_f32x2(r01);
            float2 b = unpack_f32x2(r23);
            rec[0] = a.x; rec[1] = a.y; rec[2] = b.x; rec[3] = b.y;
        }
        const float ginv[4] = {gin.x, gin.y, gin.z, gin.w};

        // elementwise dynamics
        bool z[4];
        float zf[4];
#pragma unroll
        for (int j = 0; j < 4; j++) {
            float vd   = v[j] + DT_TAU_MEM * (cur[j] - v[j]);
            float idec = cur[j] - DT_TAU_SYN * cur[j];
            float bd   = bth[j] + DT_TAU_ADAPT * (VTH - bth[j]);
            z[j]  = (vd - bd) > 0.0f;
            zf[j] = z[j] ? 1.0f : 0.0f;
            v[j]   = z[j] ? 0.0f : vd;
            bth[j] = bd + (z[j] ? BETA : 0.0f);
            cur[j] = (idec + ginv[j]) + rec[j];
            zl[j]  = zf[j];
        }

        *(float4*)(outp + (size_t)t * strideT) = make_float4(zf[0], zf[1], zf[2], zf[3]);

        // rebuild spike list (double-buffered, 2 barriers)
        int mycnt = (int)z[0] + (int)z[1] + (int)z[2] + (int)z[3];

        int inc = mycnt;
#pragma unroll
        for (int off = 1; off < 32; off *= 2) {
            int nbr = __shfl_up_sync(FULL, inc, off);
            if (lane >= off) inc += nbr;
        }
        int tex = inc - mycnt;
        if (lane == 31) s_warpcnt[wid] = inc;
        __syncthreads();

        int wc = (lane < 8) ? s_warpcnt[lane] : 0;
        int winc = wc;
#pragma unroll
        for (int off = 1; off < 8; off *= 2) {
            int nbr = __shfl_up_sync(FULL, winc, off);
            if (lane >= off) winc += nbr;
        }
        int total = __shfl_sync(FULL, winc, 7);
        int wbase = __shfl_sync(FULL, winc, wid) - __shfl_sync(FULL, wc, wid);

        const int nbuf = buf ^ 1;
        int p = wbase + tex;
        int* nl = s_list[nbuf];
        if (z[0]) nl[p++] = h0 + 0;
        if (z[1]) nl[p++] = h0 + 1;
        if (z[2]) nl[p++] = h0 + 2;
        if (z[3]) nl[p++] = h0 + 3;

        cnt = total;
        buf = nbuf;
        __syncthreads();
    }

    // final states: (zf, vf, if, bf) appended after outs [T,B,H]
    const size_t BH = (size_t)BATCH * HID;
    float* fbase = out + (size_t)T_STEPS * BH + (size_t)batch * HID + h0;
    *(float4*)(fbase + 0 * BH) = make_float4(zl[0], zl[1], zl[2], zl[3]);
    *(float4*)(fbase + 1 * BH) = make_float4(v[0], v[1], v[2], v[3]);
    *(float4*)(fbase + 2 * BH) = make_float4(cur[0], cur[1], cur[2], cur[3]);
    *(float4*)(fbase + 3 * BH) = make_float4(bth[0], bth[1], bth[2], bth[3]);
}

__global__ void __launch_bounds__(256, 2)
fused_kernel(const float* __restrict__ A, float* __restrict__ out)
{
    __shared__ __align__(16) unsigned char s_raw[SMEM_BYTES];
    if (blockIdx.x < N_SCAN_CTAS) scan_role(s_raw, out);
    else                          gemm_role(s_raw, A);
}

// ---------------------------------------------------------------------------
// Launch
// ---------------------------------------------------------------------------
extern "C" void kernel_launch(void* const* d_in, const int* in_sizes, int n_in,
                              void* d_out, int out_size)
{
    const float* x     = (const float*)d_in[0];  // [T, B, N_IN]
    const float* w_in  = (const float*)d_in[1];  // [H, N_IN]
    const float* w_rec = (const float*)d_in[2];  // [H, H]
    float* out = (float*)d_out;

    {
        dim3 blk(32, 8);
        dim3 g2(N_IN / 32, HID / 32);
        transpose_win_kernel<<<g2, blk>>>(w_in);
        dim3 g1(HID / 32, HID / 32);
        transpose_wrec_kernel<<<g1, blk>>>(w_rec);
    }

    init_flags_kernel<<<1, 256>>>();

    fused_kernel<<<N_TOTAL_CTAS, 256>>>(x, out);
}